// round 13
// baseline (speedup 1.0000x reference)
#include <cuda_runtime.h>
#include <cuda_fp16.h>
#include <cstdint>

#define NN 100000
#define NE 1600000

// ---------------- device scratch (allocation-free; ONLY touched from device code) ----------------
__device__ int   g_degi[NN];
__device__ int   g_rowptr[NN + 1];
__device__ int   g_cursor[NN];
__device__ int   g_adj[NE];
__device__ int   g_rtmp[NN];
__device__ int   g_bsum[128];
__device__ __align__(16) float  g_invdeg[NN];
// fp16 activations
__device__ __align__(16) __half g_x16[(size_t)NN * 128];
__device__ __align__(16) __half g_h116[(size_t)NN * 256];   // h1; reused as P in layer 2
__device__ __align__(16) __half g_h216[(size_t)NN * 256];
// fp16 weights: L0 [256][256]@0, L1 [256][512]@65536, L2 packed [256][256]@196608
__device__ __align__(16) __half g_wf[262144];

// fp16 plane selectors: 0 = g_x16, 1 = g_h116, 2 = g_h216
__device__ __forceinline__ const __half* sel_h(int sel) {
    if (sel == 1) return g_h116;
    if (sel == 2) return g_h216;
    return g_x16;
}

// ---------------- helpers ----------------
__device__ __forceinline__ void hacc(uint32_t u, float& a, float& b) {
    __half2 t = *reinterpret_cast<__half2*>(&u);
    float2 f = __half22float2(t);
    a += f.x; b += f.y;
}
__device__ __forceinline__ uint32_t packh2(float a, float b) {
    __half2 t = __floats2half2_rn(a, b);
    return *reinterpret_cast<uint32_t*>(&t);
}
__device__ __forceinline__ uint32_t smem_u32(const void* p) {
    uint32_t r;
    asm("{ .reg .u64 t; cvta.to.shared.u64 t, %1; cvt.u32.u64 %0, t; }" : "=r"(r) : "l"(p));
    return r;
}
__device__ __forceinline__ void cp16(uint32_t smem, const void* g) {
    asm volatile("cp.async.cg.shared.global [%0], [%1], 16;"
                 :: "r"(smem), "l"(g) : "memory");
}
#define CP_COMMIT() asm volatile("cp.async.commit_group;" ::: "memory")
template <int Nw>
__device__ __forceinline__ void cp_wait() {
    asm volatile("cp.async.wait_group %0;" :: "n"(Nw) : "memory");
}
__device__ __forceinline__ void ldmx4(uint32_t* r, uint32_t addr) {
    asm volatile("ldmatrix.sync.aligned.m8n8.x4.shared.b16 {%0,%1,%2,%3}, [%4];"
                 : "=r"(r[0]), "=r"(r[1]), "=r"(r[2]), "=r"(r[3]) : "r"(addr));
}
__device__ __forceinline__ void mma16816(float* c, const uint32_t* a, uint32_t b0, uint32_t b1) {
    asm volatile("mma.sync.aligned.m16n8k16.row.col.f32.f16.f16.f32 "
                 "{%0,%1,%2,%3}, {%4,%5,%6,%7}, {%8,%9}, {%0,%1,%2,%3};"
                 : "+f"(c[0]), "+f"(c[1]), "+f"(c[2]), "+f"(c[3])
                 : "r"(a[0]), "r"(a[1]), "r"(a[2]), "r"(a[3]), "r"(b0), "r"(b1));
}

// ---------------- CSR build ----------------
__global__ void zero_deg_kernel(int n) {
    int i = blockIdx.x * blockDim.x + threadIdx.x;
    if (i < n) g_degi[i] = 0;
}
__global__ void hist_kernel(const int* __restrict__ dst, int E, int n) {
    int i = blockIdx.x * blockDim.x + threadIdx.x;
    int stride = gridDim.x * blockDim.x;
    for (; i < E; i += stride) {
        int d = dst[i];
        if ((unsigned)d < (unsigned)n) atomicAdd(&g_degi[d], 1);
    }
}
__global__ void scan1(int n) {
    __shared__ int ws[32];
    int b = blockIdx.x, tid = threadIdx.x;
    int lane = tid & 31, wid = tid >> 5;
    int i = b * 1024 + tid;
    int v = (i < n) ? g_degi[i] : 0;
    int s = v;
    #pragma unroll
    for (int off = 1; off < 32; off <<= 1) {
        int t = __shfl_up_sync(0xffffffffu, s, off);
        if (lane >= off) s += t;
    }
    if (lane == 31) ws[wid] = s;
    __syncthreads();
    if (wid == 0) {
        int t2 = (lane < 32) ? ws[lane] : 0;
        #pragma unroll
        for (int off = 1; off < 32; off <<= 1) {
            int t = __shfl_up_sync(0xffffffffu, t2, off);
            if (lane >= off) t2 += t;
        }
        ws[lane] = t2;
    }
    __syncthreads();
    int excl = s - v + (wid ? ws[wid - 1] : 0);
    if (i < n) g_rtmp[i] = excl;
    if (tid == 1023) g_bsum[b] = excl + v;
}
__global__ void scan2(int nb) {
    __shared__ int ws[4];
    int tid = threadIdx.x, lane = tid & 31, wid = tid >> 5;
    int v = (tid < nb) ? g_bsum[tid] : 0;
    int s = v;
    #pragma unroll
    for (int off = 1; off < 32; off <<= 1) {
        int t = __shfl_up_sync(0xffffffffu, s, off);
        if (lane >= off) s += t;
    }
    if (lane == 31) ws[wid] = s;
    __syncthreads();
    if (tid == 0) {
        int a = 0;
        #pragma unroll
        for (int q = 0; q < 4; q++) { int t = ws[q]; ws[q] = a; a += t; }
    }
    __syncthreads();
    int excl = s - v + ws[wid];
    if (tid < nb) g_bsum[tid] = excl;
}
__global__ void scan3(int n) {
    int i = blockIdx.x * blockDim.x + threadIdx.x;
    if (i < n) {
        int deg = g_degi[i];
        int r = g_rtmp[i] + g_bsum[i >> 10];
        g_rowptr[i] = r;
        g_cursor[i] = r;
        g_invdeg[i] = 1.0f / fmaxf((float)deg, 1.0f);
        if (i == n - 1) g_rowptr[n] = r + deg;
    }
}
__global__ void fill_kernel(const int* __restrict__ src, const int* __restrict__ dst, int E, int n) {
    int i = blockIdx.x * blockDim.x + threadIdx.x;
    int stride = gridDim.x * blockDim.x;
    for (; i < E; i += stride) {
        int d = dst[i], s = src[i];
        if ((unsigned)d < (unsigned)n && (unsigned)s < (unsigned)n) {
            int slot = atomicAdd(&g_cursor[d], 1);
            if ((unsigned)slot < (unsigned)NE) g_adj[slot] = s;
        }
    }
}

// ---------------- prep ----------------
__global__ void prep_w_all(const float* __restrict__ Wl0, const float* __restrict__ Wr0,
                           const float* __restrict__ Wl1, const float* __restrict__ Wr1,
                           const float* __restrict__ Wl2, const float* __restrict__ Wr2) {
    for (int i = blockIdx.x * blockDim.x + threadIdx.x; i < 262144; i += gridDim.x * blockDim.x) {
        float w;
        if (i < 65536) {            // L0: K2=256
            int n = i >> 8, k = i & 255;
            w = (k < 128) ? Wl0[(size_t)k * 256 + n] : Wr0[(size_t)(k - 128) * 256 + n];
        } else if (i < 196608) {    // L1: K2=512
            int j = i - 65536;
            int n = j >> 9, k = j & 511;
            w = (k < 256) ? Wl1[(size_t)k * 256 + n] : Wr1[(size_t)(k - 256) * 256 + n];
        } else {                    // L2 packed: rows 0-127 Wl2, 128-255 Wr2; K=256
            int j = i - 196608;
            int n = j >> 8, k = j & 255;
            w = (n < 128) ? Wl2[(size_t)k * 128 + n] : Wr2[(size_t)k * 128 + (n - 128)];
        }
        g_wf[i] = __float2half(w);
    }
}
__global__ void conv_x(const float* __restrict__ x, int total4) {
    for (int i = blockIdx.x * blockDim.x + threadIdx.x; i < total4; i += gridDim.x * blockDim.x) {
        float4 v = *(const float4*)(x + (size_t)i * 4);
        *(uint2*)(g_x16 + (size_t)i * 4) = make_uint2(packh2(v.x, v.y), packh2(v.z, v.w));
    }
}

// ---------------- final: out[w] += mean-gather of P (g_h116, D=128 fp16) ----------------
__global__ void __launch_bounds__(256) agg_add(float* __restrict__ out, int n) {
    int w = (blockIdx.x * blockDim.x + threadIdx.x) >> 5;
    int lane = threadIdx.x & 31;
    if (w >= n) return;
    int j = g_rowptr[w], end = g_rowptr[w + 1];
    float acc[4] = {0.f, 0.f, 0.f, 0.f};
    for (; j + 3 < end; j += 4) {
        int s0 = g_adj[j], s1 = g_adj[j + 1], s2 = g_adj[j + 2], s3 = g_adj[j + 3];
        uint2 va = *(const uint2*)(g_h116 + (size_t)s0 * 128 + lane * 4);
        uint2 vb = *(const uint2*)(g_h116 + (size_t)s1 * 128 + lane * 4);
        uint2 vc = *(const uint2*)(g_h116 + (size_t)s2 * 128 + lane * 4);
        uint2 vd = *(const uint2*)(g_h116 + (size_t)s3 * 128 + lane * 4);
        hacc(va.x, acc[0], acc[1]); hacc(va.y, acc[2], acc[3]);
        hacc(vb.x, acc[0], acc[1]); hacc(vb.y, acc[2], acc[3]);
        hacc(vc.x, acc[0], acc[1]); hacc(vc.y, acc[2], acc[3]);
        hacc(vd.x, acc[0], acc[1]); hacc(vd.y, acc[2], acc[3]);
    }
    for (; j < end; j++) {
        int s0 = g_adj[j];
        uint2 va = *(const uint2*)(g_h116 + (size_t)s0 * 128 + lane * 4);
        hacc(va.x, acc[0], acc[1]); hacc(va.y, acc[2], acc[3]);
    }
    float sc = g_invdeg[w];
    float4* op = (float4*)(out + (size_t)w * 128 + lane * 4);
    float4 cur = *op;
    cur.x += acc[0] * sc; cur.y += acc[1] * sc;
    cur.z += acc[2] * sc; cur.w += acc[3] * sc;
    *op = cur;
}

// ---------------- fused gather + tensor-core GEMM ----------------
// BM=64, BN=256, 256 threads (8 warps, warp tile 32x64). 3-stage cp.async ring for W (+h chunks).
// DUAL: A = [agg(h) | h]; agg computed in-kernel into persistent smem.
// OUTMODE: 1 = fp16 plane out_sel (+bias, RELU); 2 = cols<128 -> P fp16 g_h116 (no bias),
//          cols>=128 -> fp32 out_ext (+bias).
template <int KA, bool DUAL, bool RELU, int OUTMODE>
__global__ void __launch_bounds__(256, 2) gemm_fused(
    int x_sel, const float* __restrict__ bias,
    float* __restrict__ out_ext, int out_sel, int wboff, int M) {
    extern __shared__ __align__(16) __half smp[];
    const uint32_t smb = smem_u32(smp);

    constexpr int K = KA / 2;                      // per-source width (DUAL)
    constexpr int CH = KA / 32;                    // total k-chunks
    constexpr int GC = DUAL ? K / 32 : 0;          // chunks served from persistent agg smem
    constexpr int PADA = DUAL ? (K + 8) : 8;       // persistent agg row stride (halves)
    constexpr int AGGSZ = DUAL ? 64 * PADA : 0;    // persistent agg size (halves)
    constexpr int SS = 64 * 40 + 256 * 40;         // ring stage size (halves): A-h + B
    constexpr int ASTRIDE = DUAL ? K : KA;

    const __half* Ax = sel_h(x_sel);
    const __half* wb = g_wf + wboff;

    int tid = threadIdx.x;
    int wid = tid >> 5, lane = tid & 31;
    int bm = blockIdx.x * 64;
    int wm = (wid & 1) * 32;
    int wn = (wid >> 1) * 64;

    float acc[2][8][4];
    #pragma unroll
    for (int i = 0; i < 2; i++)
        #pragma unroll
        for (int j = 0; j < 8; j++)
            #pragma unroll
            for (int q = 0; q < 4; q++) acc[i][j][q] = 0.f;

    // ---- ring issue: B chunk always; A-h chunk only for c >= GC ----
    auto issue = [&](int c, int st) {
        int kk = c * 32;
        // B: thread -> W row tid, 64B
        const __half* bp = wb + (size_t)tid * KA + kk;
        uint32_t bb = smb + (uint32_t)(AGGSZ + st * SS + 64 * 40 + tid * 40) * 2;
        cp16(bb, bp); cp16(bb + 16, bp + 8);
        cp16(bb + 32, bp + 16); cp16(bb + 48, bp + 24);
        if (!DUAL || c >= GC) {
            int row = tid >> 2, seg = tid & 3;
            int grow = bm + row; if (grow >= M) grow = M - 1;
            int col0 = DUAL ? (kk - K) : kk;
            const __half* ap = Ax + (size_t)grow * ASTRIDE + col0 + seg * 8;
            cp16(smb + (uint32_t)(AGGSZ + st * SS + row * 40 + seg * 8) * 2, ap);
        }
        CP_COMMIT();
    };

    issue(0, 0);
    issue(1, 1);

    // ---- gather/aggregate phase (DUAL): 8 rows per warp into persistent smem ----
    if (DUAL) {
        #pragma unroll 1
        for (int r = wid * 8; r < wid * 8 + 8; r++) {
            int grow = bm + r; if (grow >= M) grow = M - 1;
            int j = g_rowptr[grow], e = g_rowptr[grow + 1];
            float sc = g_invdeg[grow];
            if (K == 256) {
                float a[8] = {0.f, 0.f, 0.f, 0.f, 0.f, 0.f, 0.f, 0.f};
                for (; j + 1 < e; j += 2) {
                    int s0 = g_adj[j], s1 = g_adj[j + 1];
                    uint4 va = *(const uint4*)(Ax + (size_t)s0 * 256 + lane * 8);
                    uint4 vb = *(const uint4*)(Ax + (size_t)s1 * 256 + lane * 8);
                    hacc(va.x, a[0], a[1]); hacc(va.y, a[2], a[3]);
                    hacc(va.z, a[4], a[5]); hacc(va.w, a[6], a[7]);
                    hacc(vb.x, a[0], a[1]); hacc(vb.y, a[2], a[3]);
                    hacc(vb.z, a[4], a[5]); hacc(vb.w, a[6], a[7]);
                }
                if (j < e) {
                    int s0 = g_adj[j];
                    uint4 va = *(const uint4*)(Ax + (size_t)s0 * 256 + lane * 8);
                    hacc(va.x, a[0], a[1]); hacc(va.y, a[2], a[3]);
                    hacc(va.z, a[4], a[5]); hacc(va.w, a[6], a[7]);
                }
                uint4 o;
                o.x = packh2(a[0] * sc, a[1] * sc);
                o.y = packh2(a[2] * sc, a[3] * sc);
                o.z = packh2(a[4] * sc, a[5] * sc);
                o.w = packh2(a[6] * sc, a[7] * sc);
                *(uint4*)&smp[r * PADA + lane * 8] = o;
            } else {
                float a[4] = {0.f, 0.f, 0.f, 0.f};
                for (; j + 1 < e; j += 2) {
                    int s0 = g_adj[j], s1 = g_adj[j + 1];
                    uint2 va = *(const uint2*)(Ax + (size_t)s0 * 128 + lane * 4);
                    uint2 vb = *(const uint2*)(Ax + (size_t)s1 * 128 + lane * 4);
                    hacc(va.x, a[0], a[1]); hacc(va.y, a[2], a[3]);
                    hacc(vb.x, a[0], a[1]); hacc(vb.y, a[2], a[3]);
                }
                if (j < e) {
                    int s0 = g_adj[j];
                    uint2 va = *(const uint2*)(Ax + (size_t)s0 * 128 + lane * 4);
                    hacc(va.x, a[0], a[1]); hacc(va.y, a[2], a[3]);
                }
                *(uint2*)&smp[r * PADA + lane * 4] =
                    make_uint2(packh2(a[0] * sc, a[1] * sc), packh2(a[2] * sc, a[3] * sc));
            }
        }
    }

    // ---- MMA loop (first __syncthreads also publishes the gather) ----
    #pragma unroll 1
    for (int c = 0; c < CH; c++) {
        int st = c % 3;
        cp_wait<1>();
        __syncthreads();
        if (c + 2 < CH) issue(c + 2, (c + 2) % 3);
        else CP_COMMIT();

        uint32_t sbb = smb + (uint32_t)(AGGSZ + st * SS + 64 * 40) * 2;
        uint32_t sab = smb + (uint32_t)(AGGSZ + st * SS) * 2;
        #pragma unroll
        for (int ks = 0; ks < 2; ks++) {
            int lrow = lane & 15, lcolsel = (lane >> 4) * 8 + ks * 16;
            uint32_t a[2][4];
            #pragma unroll
            for (int mi = 0; mi < 2; mi++) {
                uint32_t addr;
                if (DUAL && c < GC)
                    addr = smb + (uint32_t)((wm + mi * 16 + lrow) * PADA + c * 32 + lcolsel) * 2;
                else
                    addr = sab + (uint32_t)((wm + mi * 16 + lrow) * 40 + lcolsel) * 2;
                ldmx4(a[mi], addr);
            }
            #pragma unroll
            for (int nj = 0; nj < 4; nj++) {
                uint32_t bf[4];
                ldmx4(bf, sbb + (uint32_t)((wn + nj * 16 + lrow) * 40 + lcolsel) * 2);
                #pragma unroll
                for (int mi = 0; mi < 2; mi++) {
                    mma16816(acc[mi][nj * 2],     a[mi], bf[0], bf[2]);
                    mma16816(acc[mi][nj * 2 + 1], a[mi], bf[1], bf[3]);
                }
            }
        }
    }

    // ---- epilogue ----
    int tg = lane & 3, g = lane >> 2;
    __half* out16 = (out_sel == 1) ? g_h116 : g_h216;
    #pragma unroll
    for (int mi = 0; mi < 2; mi++) {
        int r0 = bm + wm + mi * 16 + g;
        int r1 = r0 + 8;
        #pragma unroll
        for (int ni = 0; ni < 8; ni++) {
            int col = wn + ni * 8 + tg * 2;
            if (OUTMODE == 1) {
                float b0 = __ldg(&bias[col]), b1 = __ldg(&bias[col + 1]);
                float v0 = acc[mi][ni][0] + b0, v1 = acc[mi][ni][1] + b1;
                float v2 = acc[mi][ni][2] + b0, v3 = acc[mi][ni][3] + b1;
                if (RELU) {
                    v0 = fmaxf(v0, 0.f); v1 = fmaxf(v1, 0.f);
                    v2 = fmaxf(v2, 0.f); v3 = fmaxf(v3, 0.f);
                }
                if (r0 < M) *(uint32_t*)(out16 + (size_t)r0 * 256 + col) = packh2(v0, v1);
                if (r1 < M) *(uint32_t*)(out16 + (size_t)r1 * 256 + col) = packh2(v2, v3);
            } else {
                int colb = col & 127;
                if (col < 128) {   // P -> g_h116 stride 128, fp16, no bias
                    if (r0 < M) *(uint32_t*)(g_h116 + (size_t)r0 * 128 + colb)
                        = packh2(acc[mi][ni][0], acc[mi][ni][1]);
                    if (r1 < M) *(uint32_t*)(g_h116 + (size_t)r1 * 128 + colb)
                        = packh2(acc[mi][ni][2], acc[mi][ni][3]);
                } else {           // Q + b2 -> fp32 out stride 128
                    float b0 = __ldg(&bias[colb]), b1 = __ldg(&bias[colb + 1]);
                    if (r0 < M) *(float2*)(out_ext + (size_t)r0 * 128 + colb)
                        = make_float2(acc[mi][ni][0] + b0, acc[mi][ni][1] + b1);
                    if (r1 < M) *(float2*)(out_ext + (size_t)r1 * 128 + colb)
                        = make_float2(acc[mi][ni][2] + b0, acc[mi][ni][3] + b1);
                }
            }
        }
    }
}

// ---------------- launch ----------------
extern "C" void kernel_launch(void* const* d_in, const int* in_sizes, int n_in,
                              void* d_out, int out_size) {
    const float* x   = (const float*)d_in[0];
    const int*   ei  = (const int*)d_in[1];     // int32 edge_index [2, E]
    const float* Wl0 = (const float*)d_in[2];
    const float* b0  = (const float*)d_in[3];
    const float* Wr0 = (const float*)d_in[4];
    const float* Wl1 = (const float*)d_in[5];
    const float* b1  = (const float*)d_in[6];
    const float* Wr1 = (const float*)d_in[7];
    const float* Wl2 = (const float*)d_in[8];
    const float* b2  = (const float*)d_in[9];
    const float* Wr2 = (const float*)d_in[10];
    float* out = (float*)d_out;

    const int E = in_sizes[1] / 2;
    const int M = in_sizes[0] / 128;
    const int* src = ei;
    const int* dst = ei + E;
    const int nb = (M + 1023) / 1024;

    // smem sizes (bytes): persistent agg + 3 ring stages
    const int SS_B = (64 * 40 + 256 * 40) * 2;          // 25600
    const int SM_L0 = 64 * 136 * 2 + 3 * SS_B;           // 94208
    const int SM_L1 = 64 * 264 * 2 + 3 * SS_B;           // 110592
    const int SM_L2 = 3 * SS_B;                          // 76800

    cudaFuncSetAttribute(gemm_fused<256, true, true, 1>,
                         cudaFuncAttributeMaxDynamicSharedMemorySize, SM_L0);
    cudaFuncSetAttribute(gemm_fused<512, true, true, 1>,
                         cudaFuncAttributeMaxDynamicSharedMemorySize, SM_L1);
    cudaFuncSetAttribute(gemm_fused<256, false, false, 2>,
                         cudaFuncAttributeMaxDynamicSharedMemorySize, SM_L2);

    // --- CSR build ---
    zero_deg_kernel<<<(M + 255) / 256, 256>>>(M);
    hist_kernel<<<2048, 256>>>(dst, E, M);
    scan1<<<nb, 1024>>>(M);
    scan2<<<1, 128>>>(nb);
    scan3<<<(M + 255) / 256, 256>>>(M);
    fill_kernel<<<2048, 256>>>(src, dst, E, M);

    // --- prep ---
    prep_w_all<<<1024, 256>>>(Wl0, Wr0, Wl1, Wr1, Wl2, Wr2);
    conv_x<<<2048, 256>>>(x, M * 32);

    const int gx = (M + 63) / 64;
    const int agg_blocks = (M * 32 + 255) / 256;

    // --- layer 0: 128 -> 256, relu.  h1 = relu([agg(x)|x] @ W0 + b0)
    gemm_fused<256, true, true, 1><<<gx, 256, SM_L0>>>(0, b0, nullptr, 1, 0, M);

    // --- layer 1: 256 -> 256, relu.  h2 = relu([agg(h1)|h1] @ W1 + b1)
    gemm_fused<512, true, true, 1><<<gx, 256, SM_L1>>>(1, b1, nullptr, 2, 65536, M);

    // --- layer 2 (commuted): [P|Q] = h2 @ [Wl2|Wr2]; out = Q + b2; out += mean-gather(P)
    gemm_fused<256, false, false, 2><<<gx, 256, SM_L2>>>(2, b2, out, 0, 196608, M);
    agg_add<<<agg_blocks, 256>>>(out, M);
}

// round 15
// speedup vs baseline: 1.0870x; 1.0870x over previous
#include <cuda_runtime.h>
#include <cuda_fp16.h>
#include <cstdint>

#define NN 100000
#define NE 1600000

// ---------------- device scratch ----------------
__device__ int   g_degi[NN];
__device__ int   g_rowptr[NN + 1];
__device__ int   g_cursor[NN];
__device__ int   g_adj[NE];
__device__ int   g_rtmp[NN];
__device__ int   g_bsum[128];
__device__ __align__(16) float  g_invdeg[NN];
__device__ __align__(16) __half g_x16[(size_t)NN * 128];
__device__ __align__(16) __half g_h116[(size_t)NN * 256];   // h1; reused as P in layer 2
__device__ __align__(16) __half g_h216[(size_t)NN * 256];
__device__ __align__(16) __half g_agg16[(size_t)NN * 256];
// fp16 weights: L0 [256][256]@0, L1 [256][512]@65536, L2 packed [256][256]@196608
__device__ __align__(16) __half g_wf[262144];

__device__ __forceinline__ const __half* sel_h(int sel) {
    if (sel == 1) return g_h116;
    if (sel == 2) return g_h216;
    return g_x16;
}

// ---------------- helpers ----------------
__device__ __forceinline__ void hacc(uint32_t u, float& a, float& b) {
    __half2 t = *reinterpret_cast<__half2*>(&u);
    float2 f = __half22float2(t);
    a += f.x; b += f.y;
}
__device__ __forceinline__ uint32_t packh2(float a, float b) {
    __half2 t = __floats2half2_rn(a, b);
    return *reinterpret_cast<uint32_t*>(&t);
}
__device__ __forceinline__ uint32_t smem_u32(const void* p) {
    uint32_t r;
    asm("{ .reg .u64 t; cvta.to.shared.u64 t, %1; cvt.u32.u64 %0, t; }" : "=r"(r) : "l"(p));
    return r;
}
__device__ __forceinline__ void cp16(uint32_t smem, const void* g) {
    asm volatile("cp.async.cg.shared.global [%0], [%1], 16;"
                 :: "r"(smem), "l"(g) : "memory");
}
#define CP_COMMIT() asm volatile("cp.async.commit_group;" ::: "memory")
template <int Nw>
__device__ __forceinline__ void cp_wait() {
    asm volatile("cp.async.wait_group %0;" :: "n"(Nw) : "memory");
}
__device__ __forceinline__ void ldmx4(uint32_t* r, uint32_t addr) {
    asm volatile("ldmatrix.sync.aligned.m8n8.x4.shared.b16 {%0,%1,%2,%3}, [%4];"
                 : "=r"(r[0]), "=r"(r[1]), "=r"(r[2]), "=r"(r[3]) : "r"(addr));
}
__device__ __forceinline__ void mma16816(float* c, const uint32_t* a, uint32_t b0, uint32_t b1) {
    asm volatile("mma.sync.aligned.m16n8k16.row.col.f32.f16.f16.f32 "
                 "{%0,%1,%2,%3}, {%4,%5,%6,%7}, {%8,%9}, {%0,%1,%2,%3};"
                 : "+f"(c[0]), "+f"(c[1]), "+f"(c[2]), "+f"(c[3])
                 : "r"(a[0]), "r"(a[1]), "r"(a[2]), "r"(a[3]), "r"(b0), "r"(b1));
}

// ---------------- CSR build ----------------
__global__ void scan1(int n) {
    __shared__ int ws[32];
    int b = blockIdx.x, tid = threadIdx.x;
    int lane = tid & 31, wid = tid >> 5;
    int i = b * 1024 + tid;
    int v = (i < n) ? g_degi[i] : 0;
    int s = v;
    #pragma unroll
    for (int off = 1; off < 32; off <<= 1) {
        int t = __shfl_up_sync(0xffffffffu, s, off);
        if (lane >= off) s += t;
    }
    if (lane == 31) ws[wid] = s;
    __syncthreads();
    if (wid == 0) {
        int t2 = (lane < 32) ? ws[lane] : 0;
        #pragma unroll
        for (int off = 1; off < 32; off <<= 1) {
            int t = __shfl_up_sync(0xffffffffu, t2, off);
            if (lane >= off) t2 += t;
        }
        ws[lane] = t2;
    }
    __syncthreads();
    int excl = s - v + (wid ? ws[wid - 1] : 0);
    if (i < n) g_rtmp[i] = excl;
    if (tid == 1023) g_bsum[b] = excl + v;
}
__global__ void scan2(int nb) {
    __shared__ int ws[4];
    int tid = threadIdx.x, lane = tid & 31, wid = tid >> 5;
    int v = (tid < nb) ? g_bsum[tid] : 0;
    int s = v;
    #pragma unroll
    for (int off = 1; off < 32; off <<= 1) {
        int t = __shfl_up_sync(0xffffffffu, s, off);
        if (lane >= off) s += t;
    }
    if (lane == 31) ws[wid] = s;
    __syncthreads();
    if (tid == 0) {
        int a = 0;
        #pragma unroll
        for (int q = 0; q < 4; q++) { int t = ws[q]; ws[q] = a; a += t; }
    }
    __syncthreads();
    int excl = s - v + ws[wid];
    if (tid < nb) g_bsum[tid] = excl;
}
__global__ void scan3(int n) {
    int i = blockIdx.x * blockDim.x + threadIdx.x;
    if (i < n) {
        int deg = g_degi[i];
        int r = g_rtmp[i] + g_bsum[i >> 10];
        g_rowptr[i] = r;
        g_cursor[i] = r;
        g_invdeg[i] = 1.0f / fmaxf((float)deg, 1.0f);
        if (i == n - 1) g_rowptr[n] = r + deg;
    }
}
__global__ void fill_kernel(const int* __restrict__ src, const int* __restrict__ dst, int E, int n) {
    int i = blockIdx.x * blockDim.x + threadIdx.x;
    int stride = gridDim.x * blockDim.x;
    for (; i < E; i += stride) {
        int d = dst[i], s = src[i];
        if ((unsigned)d < (unsigned)n && (unsigned)s < (unsigned)n) {
            int slot = atomicAdd(&g_cursor[d], 1);
            if ((unsigned)slot < (unsigned)NE) g_adj[slot] = s;
        }
    }
}

// ---------------- merged init: zero degi + split all weights ----------------
__global__ void init_zero_prep(const float* __restrict__ Wl0, const float* __restrict__ Wr0,
                               const float* __restrict__ Wl1, const float* __restrict__ Wr1,
                               const float* __restrict__ Wl2, const float* __restrict__ Wr2,
                               int M) {
    int total = M + 262144;
    for (int i = blockIdx.x * blockDim.x + threadIdx.x; i < total; i += gridDim.x * blockDim.x) {
        if (i < M) { g_degi[i] = 0; continue; }
        int j = i - M;
        float w;
        if (j < 65536) {            // L0: K2=256
            int n = j >> 8, k = j & 255;
            w = (k < 128) ? Wl0[(size_t)k * 256 + n] : Wr0[(size_t)(k - 128) * 256 + n];
        } else if (j < 196608) {    // L1: K2=512
            int q = j - 65536;
            int n = q >> 9, k = q & 511;
            w = (k < 256) ? Wl1[(size_t)k * 256 + n] : Wr1[(size_t)(k - 256) * 256 + n];
        } else {                    // L2 packed
            int q = j - 196608;
            int n = q >> 8, k = q & 255;
            w = (n < 128) ? Wl2[(size_t)k * 128 + n] : Wr2[(size_t)k * 128 + (n - 128)];
        }
        g_wf[j] = __float2half(w);
    }
}
// ---------------- merged: histogram + x->fp16 convert ----------------
__global__ void hist_conv(const int* __restrict__ dst, const float* __restrict__ x,
                          int E, int n, int total4) {
    int total = E + total4;
    for (int i = blockIdx.x * blockDim.x + threadIdx.x; i < total; i += gridDim.x * blockDim.x) {
        if (i < E) {
            int d = dst[i];
            if ((unsigned)d < (unsigned)n) atomicAdd(&g_degi[d], 1);
        } else {
            int j = i - E;
            float4 v = *(const float4*)(x + (size_t)j * 4);
            *(uint2*)(g_x16 + (size_t)j * 4) = make_uint2(packh2(v.x, v.y), packh2(v.z, v.w));
        }
    }
}

// ---------------- gather body: mean over neighbors, write g_agg16 (stride K) ----------------
template <int K>
__device__ __forceinline__ void gather_one(const __half* __restrict__ feat, int w, int lane) {
    int j = g_rowptr[w], end = g_rowptr[w + 1];
    float sc = g_invdeg[w];
    if (K == 256) {
        float acc[8] = {0.f, 0.f, 0.f, 0.f, 0.f, 0.f, 0.f, 0.f};
        for (; j + 3 < end; j += 4) {
            int s0 = g_adj[j], s1 = g_adj[j + 1], s2 = g_adj[j + 2], s3 = g_adj[j + 3];
            uint4 va = *(const uint4*)(feat + (size_t)s0 * 256 + lane * 8);
            uint4 vb = *(const uint4*)(feat + (size_t)s1 * 256 + lane * 8);
            uint4 vc = *(const uint4*)(feat + (size_t)s2 * 256 + lane * 8);
            uint4 vd = *(const uint4*)(feat + (size_t)s3 * 256 + lane * 8);
            hacc(va.x, acc[0], acc[1]); hacc(va.y, acc[2], acc[3]);
            hacc(va.z, acc[4], acc[5]); hacc(va.w, acc[6], acc[7]);
            hacc(vb.x, acc[0], acc[1]); hacc(vb.y, acc[2], acc[3]);
            hacc(vb.z, acc[4], acc[5]); hacc(vb.w, acc[6], acc[7]);
            hacc(vc.x, acc[0], acc[1]); hacc(vc.y, acc[2], acc[3]);
            hacc(vc.z, acc[4], acc[5]); hacc(vc.w, acc[6], acc[7]);
            hacc(vd.x, acc[0], acc[1]); hacc(vd.y, acc[2], acc[3]);
            hacc(vd.z, acc[4], acc[5]); hacc(vd.w, acc[6], acc[7]);
        }
        for (; j < end; j++) {
            int s0 = g_adj[j];
            uint4 va = *(const uint4*)(feat + (size_t)s0 * 256 + lane * 8);
            hacc(va.x, acc[0], acc[1]); hacc(va.y, acc[2], acc[3]);
            hacc(va.z, acc[4], acc[5]); hacc(va.w, acc[6], acc[7]);
        }
        uint4 o;
        o.x = packh2(acc[0] * sc, acc[1] * sc);
        o.y = packh2(acc[2] * sc, acc[3] * sc);
        o.z = packh2(acc[4] * sc, acc[5] * sc);
        o.w = packh2(acc[6] * sc, acc[7] * sc);
        *(uint4*)(g_agg16 + (size_t)w * 256 + lane * 8) = o;
    } else {
        float acc[4] = {0.f, 0.f, 0.f, 0.f};
        for (; j + 3 < end; j += 4) {
            int s0 = g_adj[j], s1 = g_adj[j + 1], s2 = g_adj[j + 2], s3 = g_adj[j + 3];
            uint2 va = *(const uint2*)(feat + (size_t)s0 * 128 + lane * 4);
            uint2 vb = *(const uint2*)(feat + (size_t)s1 * 128 + lane * 4);
            uint2 vc = *(const uint2*)(feat + (size_t)s2 * 128 + lane * 4);
            uint2 vd = *(const uint2*)(feat + (size_t)s3 * 128 + lane * 4);
            hacc(va.x, acc[0], acc[1]); hacc(va.y, acc[2], acc[3]);
            hacc(vb.x, acc[0], acc[1]); hacc(vb.y, acc[2], acc[3]);
            hacc(vc.x, acc[0], acc[1]); hacc(vc.y, acc[2], acc[3]);
            hacc(vd.x, acc[0], acc[1]); hacc(vd.y, acc[2], acc[3]);
        }
        for (; j < end; j++) {
            int s0 = g_adj[j];
            uint2 va = *(const uint2*)(feat + (size_t)s0 * 128 + lane * 4);
            hacc(va.x, acc[0], acc[1]); hacc(va.y, acc[2], acc[3]);
        }
        *(uint2*)(g_agg16 + (size_t)w * 128 + lane * 4) =
            make_uint2(packh2(acc[0] * sc, acc[1] * sc), packh2(acc[2] * sc, acc[3] * sc));
    }
}

// ---------------- final: out[w] += mean-gather of P (g_h116, D=128 fp16) ----------------
__global__ void __launch_bounds__(256) agg_add(float* __restrict__ out, int n) {
    int w = (blockIdx.x * blockDim.x + threadIdx.x) >> 5;
    int lane = threadIdx.x & 31;
    if (w >= n) return;
    int j = g_rowptr[w], end = g_rowptr[w + 1];
    float acc[4] = {0.f, 0.f, 0.f, 0.f};
    for (; j + 3 < end; j += 4) {
        int s0 = g_adj[j], s1 = g_adj[j + 1], s2 = g_adj[j + 2], s3 = g_adj[j + 3];
        uint2 va = *(const uint2*)(g_h116 + (size_t)s0 * 128 + lane * 4);
        uint2 vb = *(const uint2*)(g_h116 + (size_t)s1 * 128 + lane * 4);
        uint2 vc = *(const uint2*)(g_h116 + (size_t)s2 * 128 + lane * 4);
        uint2 vd = *(const uint2*)(g_h116 + (size_t)s3 * 128 + lane * 4);
        hacc(va.x, acc[0], acc[1]); hacc(va.y, acc[2], acc[3]);
        hacc(vb.x, acc[0], acc[1]); hacc(vb.y, acc[2], acc[3]);
        hacc(vc.x, acc[0], acc[1]); hacc(vc.y, acc[2], acc[3]);
        hacc(vd.x, acc[0], acc[1]); hacc(vd.y, acc[2], acc[3]);
    }
    for (; j < end; j++) {
        int s0 = g_adj[j];
        uint2 va = *(const uint2*)(g_h116 + (size_t)s0 * 128 + lane * 4);
        hacc(va.x, acc[0], acc[1]); hacc(va.y, acc[2], acc[3]);
    }
    float sc = g_invdeg[w];
    float4* op = (float4*)(out + (size_t)w * 128 + lane * 4);
    float4 cur = *op;
    cur.x += acc[0] * sc; cur.y += acc[1] * sc;
    cur.z += acc[2] * sc; cur.w += acc[3] * sc;
    *op = cur;
}

// ---------------- layer kernel: gather blocks + gemm blocks in one launch ----------------
// Role by block index: with nETiles>0 and gather blocks present, every `period`-th block is
// a gemm tile; the rest are gather blocks (8 nodes each, warp-per-node).
// OUTMODE: 1 = fp16 plane out_sel (+bias, RELU); 2 = split by column (P fp16 / Q fp32+bias).
template <int KA, bool DUAL, bool RELU, int OUTMODE>
__global__ void __launch_bounds__(256, 2) layer_k(
    int x_sel, const float* __restrict__ bias,
    float* __restrict__ out_ext, int out_sel, int wboff, int M,
    int gRow0, int nGNodes, int eTile0, int nETiles, int period) {
    extern __shared__ __align__(16) __half smp[];
    const uint32_t smb = smem_u32(smp);

    int bid = blockIdx.x;
    int tid = threadIdx.x;
    int wid = tid >> 5, lane = tid & 31;
    const __half* Ax = sel_h(x_sel);

    int nGB = (nGNodes + 7) >> 3;
    bool isGemm;
    int me = 0, mg = 0;
    if (nETiles == 0)      { isGemm = false; mg = bid; }
    else if (nGB == 0)     { isGemm = true;  me = bid; }
    else {
        int q = bid / period;
        if (bid % period == 0 && q < nETiles) { isGemm = true; me = q; }
        else {
            int gemmBefore = min((bid + period - 1) / period, nETiles);
            isGemm = false; mg = bid - gemmBefore;
        }
    }

    if (!isGemm) {
        int node = gRow0 + mg * 8 + wid;
        if (node < gRow0 + nGNodes) gather_one<(DUAL ? KA / 2 : 128)>(Ax, node, lane);
        return;
    }

    // ---------------- gemm tile ----------------
    int tileIdx = eTile0 + me;
    int bm = (tileIdx >> 1) * 128;
    int bn = (tileIdx & 1) * 128;
    int wm = (wid & 3) * 32;
    int wn = (wid >> 2) * 64;
    constexpr int ASTRIDE = DUAL ? KA / 2 : KA;
    constexpr int CHUNKS = KA / 32;
    const __half* wb = g_wf + wboff;

    float acc[2][8][4];
    #pragma unroll
    for (int i = 0; i < 2; i++)
        #pragma unroll
        for (int j = 0; j < 8; j++)
            #pragma unroll
            for (int q = 0; q < 4; q++) acc[i][j][q] = 0.f;

    int lr = tid >> 1, lc = (tid & 1) * 16;
    int arow = bm + lr; if (arow >= M) arow = M - 1;

    auto issue = [&](int c, int st) {
        int kk = c * 32;
        const __half* ap;
        if (DUAL) {
            constexpr int K = KA / 2;
            const __half* Asrc = (kk < K) ? g_agg16 : Ax;
            int col0 = (kk < K) ? kk : (kk - K);
            ap = Asrc + (size_t)arow * ASTRIDE + col0 + lc;
        } else {
            ap = Ax + (size_t)arow * ASTRIDE + kk + lc;
        }
        uint32_t abase = smb + (uint32_t)(st * 5120 + lr * 40 + lc) * 2;
        cp16(abase, ap);
        cp16(abase + 16, ap + 8);
        const __half* bp = wb + (size_t)(bn + lr) * KA + kk + lc;
        uint32_t bbase = smb + (uint32_t)(15360 + st * 5120 + lr * 40 + lc) * 2;
        cp16(bbase, bp);
        cp16(bbase + 16, bp + 8);
        CP_COMMIT();
    };

    issue(0, 0);
    issue(1, 1);

    #pragma unroll 1
    for (int c = 0; c < CHUNKS; c++) {
        int st = c % 3;
        cp_wait<1>();
        __syncthreads();
        if (c + 2 < CHUNKS) issue(c + 2, (c + 2) % 3);
        else CP_COMMIT();

        uint32_t sa = smb + (uint32_t)(st * 5120) * 2;
        uint32_t sb = smb + (uint32_t)(15360 + st * 5120) * 2;
        #pragma unroll
        for (int ks = 0; ks < 2; ks++) {
            int lrow = lane & 15, lcolsel = (lane >> 4) * 8 + ks * 16;
            uint32_t a[2][4];
            #pragma unroll
            for (int mi = 0; mi < 2; mi++)
                ldmx4(a[mi], sa + (uint32_t)((wm + mi * 16 + lrow) * 40 + lcolsel) * 2);
            #pragma unroll
            for (int nj = 0; nj < 4; nj++) {
                uint32_t bf[4];
                ldmx4(bf, sb + (uint32_t)((wn + nj * 16 + lrow) * 40 + lcolsel) * 2);
                #pragma unroll
                for (int mi = 0; mi < 2; mi++) {
                    mma16816(acc[mi][nj * 2],     a[mi], bf[0], bf[2]);
                    mma16816(acc[mi][nj * 2 + 1], a[mi], bf[1], bf[3]);
                }
            }
        }
    }

    // ---- epilogue ----
    int tg = lane & 3, g = lane >> 2;
    __half* out16 = (out_sel == 1) ? g_h116 : g_h216;
    bool isP = (OUTMODE == 2) && (bn == 0);
    #pragma unroll
    for (int mi = 0; mi < 2; mi++) {
        int r0 = bm + wm + mi * 16 + g;
        int r1 = r0 + 8;
        #pragma unroll
        for (int ni = 0; ni < 8; ni++) {
            int col = bn + wn + ni * 8 + tg * 2;
            int colb = (OUTMODE == 2) ? (col & 127) : col;
            float b0 = isP ? 0.f : __ldg(&bias[colb]);
            float b1 = isP ? 0.f : __ldg(&bias[colb + 1]);
            float v0 = acc[mi][ni][0] + b0, v1 = acc[mi][ni][1] + b1;
            float v2 = acc[mi][ni][2] + b0, v3 = acc[mi][ni][3] + b1;
            if (RELU) {
                v0 = fmaxf(v0, 0.f); v1 = fmaxf(v1, 0.f);
                v2 = fmaxf(v2, 0.f); v3 = fmaxf(v3, 0.f);
            }
            if (OUTMODE == 1) {
                if (r0 < M) *(uint32_t*)(out16 + (size_t)r0 * 256 + col) = packh2(v0, v1);
                if (r1 < M) *(uint32_t*)(out16 + (size_t)r1 * 256 + col) = packh2(v2, v3);
            } else {
                if (isP) {
                    if (r0 < M) *(uint32_t*)(g_h116 + (size_t)r0 * 128 + colb) = packh2(v0, v1);
                    if (r1 < M) *(uint32_t*)(g_h116 + (size_t)r1 * 128 + colb) = packh2(v2, v3);
                } else {
                    if (r0 < M) *(float2*)(out_ext + (size_t)r0 * 128 + colb) = make_float2(v0, v1);
                    if (r1 < M) *(float2*)(out_ext + (size_t)r1 * 128 + colb) = make_float2(v2, v3);
                }
            }
        }
    }
}

// ---------------- launch ----------------
extern "C" void kernel_launch(void* const* d_in, const int* in_sizes, int n_in,
                              void* d_out, int out_size) {
    const float* x   = (const float*)d_in[0];
    const int*   ei  = (const int*)d_in[1];     // int32 edge_index [2, E]
    const float* Wl0 = (const float*)d_in[2];
    const float* b0  = (const float*)d_in[3];
    const float* Wr0 = (const float*)d_in[4];
    const float* Wl1 = (const float*)d_in[5];
    const float* b1  = (const float*)d_in[6];
    const float* Wr1 = (const float*)d_in[7];
    const float* Wl2 = (const float*)d_in[8];
    const float* b2  = (const float*)d_in[9];
    const float* Wr2 = (const float*)d_in[10];
    float* out = (float*)d_out;

    const int E = in_sizes[1] / 2;
    const int M = in_sizes[0] / 128;
    const int* src = ei;
    const int* dst = ei + E;
    const int nb = (M + 1023) / 1024;
    const int SMEM = 3 * 5120 * 2 * 2;   // 61440 bytes

    cudaFuncSetAttribute(layer_k<256, true, true, 1>,
                         cudaFuncAttributeMaxDynamicSharedMemorySize, SMEM);
    cudaFuncSetAttribute(layer_k<512, true, true, 1>,
                         cudaFuncAttributeMaxDynamicSharedMemorySize, SMEM);
    cudaFuncSetAttribute(layer_k<256, false, false, 2>,
                         cudaFuncAttributeMaxDynamicSharedMemorySize, SMEM);

    // chunking: rows [0, Mh) = chunk A, [Mh, M) = chunk B (Mh 128-aligned)
    const int TM = (M + 127) / 128;                       // total m-tiles
    int Mh = ((M / 2 + 127) / 128) * 128;
    if (Mh > M) Mh = M;
    const int tilesA = Mh / 128, tilesB = TM - tilesA;
    const int nodesA = Mh, nodesB = M - Mh;
    const int gbA = (nodesA + 7) / 8, gbB = (nodesB + 7) / 8;
    const int ebA = tilesA * 2, ebB = tilesB * 2;
    const int gridK2 = gbB + ebA;
    const int perK2 = (ebA > 0) ? ((gridK2 / ebA > 0) ? gridK2 / ebA : 1) : 1;

    // --- CSR build; zero+prep merged; hist+conv merged ---
    init_zero_prep<<<1024, 256>>>(Wl0, Wr0, Wl1, Wr1, Wl2, Wr2, M);
    hist_conv<<<2048, 256>>>(dst, x, E, M, M * 32);
    scan1<<<nb, 1024>>>(M);
    scan2<<<1, 128>>>(nb);
    scan3<<<(M + 255) / 256, 256>>>(M);
    fill_kernel<<<2048, 256>>>(src, dst, E, M);

    const int agg_blocks = (M * 32 + 255) / 256;

    // --- layer 0: 128 -> 256, relu ---
    layer_k<256, true, true, 1><<<gbA, 256>>>(0, b0, nullptr, 1, 0, M,
                                              0, nodesA, 0, 0, 1);
    layer_k<256, true, true, 1><<<gridK2, 256, SMEM>>>(0, b0, nullptr, 1, 0, M,
                                                       Mh, nodesB, 0, ebA, perK2);
    layer_k<256, true, true, 1><<<ebB, 256, SMEM>>>(0, b0, nullptr, 1, 0, M,
                                                    0, 0, ebA, ebB, 1);

    // --- layer 1: 256 -> 256, relu ---
    layer_k<512, true, true, 1><<<gbA, 256>>>(1, b1, nullptr, 2, 65536, M,
                                              0, nodesA, 0, 0, 1);
    layer_k<512, true, true, 1><<<gridK2, 256, SMEM>>>(1, b1, nullptr, 2, 65536, M,
                                                       Mh, nodesB, 0, ebA, perK2);
    layer_k<512, true, true, 1><<<ebB, 256, SMEM>>>(1, b1, nullptr, 2, 65536, M,
                                                    0, 0, ebA, ebB, 1);

    // --- layer 2 (commuted): [P|Q] = h2 @ [Wl2|Wr2]; out = Q + b2; out += mean-gather(P) ---
    layer_k<256, false, false, 2><<<TM * 2, 256, SMEM>>>(2, b2, out, 0, 196608, M,
                                                         0, 0, 0, TM * 2, 1);
    agg_add<<<agg_blocks, 256>>>(out, M);
}

// round 16
// speedup vs baseline: 1.4959x; 1.3761x over previous
#include <cuda_runtime.h>
#include <cuda_fp16.h>
#include <cstdint>

#define NN 100000
#define NE 1600000

// ---------------- device scratch (allocation-free; ONLY touched from device code) ----------------
__device__ int   g_degi[NN];
__device__ int   g_rowptr[NN + 1];
__device__ int   g_cursor[NN];
__device__ int   g_adj[NE];
__device__ int   g_rtmp[NN];
__device__ int   g_bsum[128];
__device__ __align__(16) float  g_invdeg[NN];
// fp16 activations
__device__ __align__(16) __half g_x16[(size_t)NN * 128];
__device__ __align__(16) __half g_h116[(size_t)NN * 256];   // h1; reused as P in layer 2
__device__ __align__(16) __half g_h216[(size_t)NN * 256];
__device__ __align__(16) __half g_agg16[(size_t)NN * 256];
// fp16 weights: L0 [256][256]@0, L1 [256][512]@65536, L2 packed [256][256]@196608
__device__ __align__(16) __half g_wf[262144];

// fp16 plane selectors: 0 = g_x16, 1 = g_h116, 2 = g_h216
__device__ __forceinline__ const __half* sel_h(int sel) {
    if (sel == 1) return g_h116;
    if (sel == 2) return g_h216;
    return g_x16;
}

// ---------------- helpers ----------------
__device__ __forceinline__ void hacc(uint32_t u, float& a, float& b) {
    __half2 t = *reinterpret_cast<__half2*>(&u);
    float2 f = __half22float2(t);
    a += f.x; b += f.y;
}
__device__ __forceinline__ uint32_t packh2(float a, float b) {
    __half2 t = __floats2half2_rn(a, b);
    return *reinterpret_cast<uint32_t*>(&t);
}
__device__ __forceinline__ uint32_t smem_u32(const void* p) {
    uint32_t r;
    asm("{ .reg .u64 t; cvta.to.shared.u64 t, %1; cvt.u32.u64 %0, t; }" : "=r"(r) : "l"(p));
    return r;
}
__device__ __forceinline__ void cp16(uint32_t smem, const void* g) {
    asm volatile("cp.async.cg.shared.global [%0], [%1], 16;"
                 :: "r"(smem), "l"(g) : "memory");
}
#define CP_COMMIT() asm volatile("cp.async.commit_group;" ::: "memory")
template <int Nw>
__device__ __forceinline__ void cp_wait() {
    asm volatile("cp.async.wait_group %0;" :: "n"(Nw) : "memory");
}
__device__ __forceinline__ void ldmx4(uint32_t* r, uint32_t addr) {
    asm volatile("ldmatrix.sync.aligned.m8n8.x4.shared.b16 {%0,%1,%2,%3}, [%4];"
                 : "=r"(r[0]), "=r"(r[1]), "=r"(r[2]), "=r"(r[3]) : "r"(addr));
}
__device__ __forceinline__ void mma16816(float* c, const uint32_t* a, uint32_t b0, uint32_t b1) {
    asm volatile("mma.sync.aligned.m16n8k16.row.col.f32.f16.f16.f32 "
                 "{%0,%1,%2,%3}, {%4,%5,%6,%7}, {%8,%9}, {%0,%1,%2,%3};"
                 : "+f"(c[0]), "+f"(c[1]), "+f"(c[2]), "+f"(c[3])
                 : "r"(a[0]), "r"(a[1]), "r"(a[2]), "r"(a[3]), "r"(b0), "r"(b1));
}

// ---------------- CSR build ----------------
__global__ void scan1(int n) {
    __shared__ int ws[32];
    int b = blockIdx.x, tid = threadIdx.x;
    int lane = tid & 31, wid = tid >> 5;
    int i = b * 1024 + tid;
    int v = (i < n) ? g_degi[i] : 0;
    int s = v;
    #pragma unroll
    for (int off = 1; off < 32; off <<= 1) {
        int t = __shfl_up_sync(0xffffffffu, s, off);
        if (lane >= off) s += t;
    }
    if (lane == 31) ws[wid] = s;
    __syncthreads();
    if (wid == 0) {
        int t2 = (lane < 32) ? ws[lane] : 0;
        #pragma unroll
        for (int off = 1; off < 32; off <<= 1) {
            int t = __shfl_up_sync(0xffffffffu, t2, off);
            if (lane >= off) t2 += t;
        }
        ws[lane] = t2;
    }
    __syncthreads();
    int excl = s - v + (wid ? ws[wid - 1] : 0);
    if (i < n) g_rtmp[i] = excl;
    if (tid == 1023) g_bsum[b] = excl + v;
}
__global__ void scan2(int nb) {
    __shared__ int ws[4];
    int tid = threadIdx.x, lane = tid & 31, wid = tid >> 5;
    int v = (tid < nb) ? g_bsum[tid] : 0;
    int s = v;
    #pragma unroll
    for (int off = 1; off < 32; off <<= 1) {
        int t = __shfl_up_sync(0xffffffffu, s, off);
        if (lane >= off) s += t;
    }
    if (lane == 31) ws[wid] = s;
    __syncthreads();
    if (tid == 0) {
        int a = 0;
        #pragma unroll
        for (int q = 0; q < 4; q++) { int t = ws[q]; ws[q] = a; a += t; }
    }
    __syncthreads();
    int excl = s - v + ws[wid];
    if (tid < nb) g_bsum[tid] = excl;
}
// scan3 + invdeg fused
__global__ void scan3(int n) {
    int i = blockIdx.x * blockDim.x + threadIdx.x;
    if (i < n) {
        int deg = g_degi[i];
        int r = g_rtmp[i] + g_bsum[i >> 10];
        g_rowptr[i] = r;
        g_cursor[i] = r;
        g_invdeg[i] = 1.0f / fmaxf((float)deg, 1.0f);
        if (i == n - 1) g_rowptr[n] = r + deg;
    }
}
__global__ void fill_kernel(const int* __restrict__ src, const int* __restrict__ dst, int E, int n) {
    int i = blockIdx.x * blockDim.x + threadIdx.x;
    int stride = gridDim.x * blockDim.x;
    for (; i < E; i += stride) {
        int d = dst[i], s = src[i];
        if ((unsigned)d < (unsigned)n && (unsigned)s < (unsigned)n) {
            int slot = atomicAdd(&g_cursor[d], 1);
            if ((unsigned)slot < (unsigned)NE) g_adj[slot] = s;
        }
    }
}

// ---------------- merged init: zero degi + split all weights ----------------
__global__ void init_zero_prep(const float* __restrict__ Wl0, const float* __restrict__ Wr0,
                               const float* __restrict__ Wl1, const float* __restrict__ Wr1,
                               const float* __restrict__ Wl2, const float* __restrict__ Wr2,
                               int M) {
    int total = M + 262144;
    for (int i = blockIdx.x * blockDim.x + threadIdx.x; i < total; i += gridDim.x * blockDim.x) {
        if (i < M) { g_degi[i] = 0; continue; }
        int j = i - M;
        float w;
        if (j < 65536) {            // L0: K2=256
            int n = j >> 8, k = j & 255;
            w = (k < 128) ? Wl0[(size_t)k * 256 + n] : Wr0[(size_t)(k - 128) * 256 + n];
        } else if (j < 196608) {    // L1: K2=512
            int q = j - 65536;
            int n = q >> 9, k = q & 511;
            w = (k < 256) ? Wl1[(size_t)k * 256 + n] : Wr1[(size_t)(k - 256) * 256 + n];
        } else {                    // L2 packed: rows 0-127 Wl2 cols, 128-255 Wr2 cols; K=256
            int q = j - 196608;
            int n = q >> 8, k = q & 255;
            w = (n < 128) ? Wl2[(size_t)k * 128 + n] : Wr2[(size_t)k * 128 + (n - 128)];
        }
        g_wf[j] = __float2half(w);
    }
}
// ---------------- merged: histogram + x->fp16 convert ----------------
__global__ void hist_conv(const int* __restrict__ dst, const float* __restrict__ x,
                          int E, int n, int total4) {
    int total = E + total4;
    for (int i = blockIdx.x * blockDim.x + threadIdx.x; i < total; i += gridDim.x * blockDim.x) {
        if (i < E) {
            int d = dst[i];
            if ((unsigned)d < (unsigned)n) atomicAdd(&g_degi[d], 1);
        } else {
            int j = i - E;
            float4 v = *(const float4*)(x + (size_t)j * 4);
            *(uint2*)(g_x16 + (size_t)j * 4) = make_uint2(packh2(v.x, v.y), packh2(v.z, v.w));
        }
    }
}

// ---------------- mean aggregation: fp16 gather, fp32 accumulate, fp16 write ----------------
template <int D>
__global__ void __launch_bounds__(256) aggregate_kernel(int src_sel, int n) {
    const __half* feat = sel_h(src_sel);
    int w = (blockIdx.x * blockDim.x + threadIdx.x) >> 5;
    int lane = threadIdx.x & 31;
    if (w >= n) return;
    int j = g_rowptr[w], end = g_rowptr[w + 1];

    if (D == 256) {
        float acc[8] = {0.f, 0.f, 0.f, 0.f, 0.f, 0.f, 0.f, 0.f};
        for (; j + 3 < end; j += 4) {
            int s0 = g_adj[j], s1 = g_adj[j + 1], s2 = g_adj[j + 2], s3 = g_adj[j + 3];
            uint4 va = *(const uint4*)(feat + (size_t)s0 * 256 + lane * 8);
            uint4 vb = *(const uint4*)(feat + (size_t)s1 * 256 + lane * 8);
            uint4 vc = *(const uint4*)(feat + (size_t)s2 * 256 + lane * 8);
            uint4 vd = *(const uint4*)(feat + (size_t)s3 * 256 + lane * 8);
            hacc(va.x, acc[0], acc[1]); hacc(va.y, acc[2], acc[3]);
            hacc(va.z, acc[4], acc[5]); hacc(va.w, acc[6], acc[7]);
            hacc(vb.x, acc[0], acc[1]); hacc(vb.y, acc[2], acc[3]);
            hacc(vb.z, acc[4], acc[5]); hacc(vb.w, acc[6], acc[7]);
            hacc(vc.x, acc[0], acc[1]); hacc(vc.y, acc[2], acc[3]);
            hacc(vc.z, acc[4], acc[5]); hacc(vc.w, acc[6], acc[7]);
            hacc(vd.x, acc[0], acc[1]); hacc(vd.y, acc[2], acc[3]);
            hacc(vd.z, acc[4], acc[5]); hacc(vd.w, acc[6], acc[7]);
        }
        for (; j < end; j++) {
            int s0 = g_adj[j];
            uint4 va = *(const uint4*)(feat + (size_t)s0 * 256 + lane * 8);
            hacc(va.x, acc[0], acc[1]); hacc(va.y, acc[2], acc[3]);
            hacc(va.z, acc[4], acc[5]); hacc(va.w, acc[6], acc[7]);
        }
        float sc = g_invdeg[w];
        uint4 o;
        o.x = packh2(acc[0] * sc, acc[1] * sc);
        o.y = packh2(acc[2] * sc, acc[3] * sc);
        o.z = packh2(acc[4] * sc, acc[5] * sc);
        o.w = packh2(acc[6] * sc, acc[7] * sc);
        *(uint4*)(g_agg16 + (size_t)w * 256 + lane * 8) = o;
    } else {
        float acc[4] = {0.f, 0.f, 0.f, 0.f};
        for (; j + 3 < end; j += 4) {
            int s0 = g_adj[j], s1 = g_adj[j + 1], s2 = g_adj[j + 2], s3 = g_adj[j + 3];
            uint2 va = *(const uint2*)(feat + (size_t)s0 * 128 + lane * 4);
            uint2 vb = *(const uint2*)(feat + (size_t)s1 * 128 + lane * 4);
            uint2 vc = *(const uint2*)(feat + (size_t)s2 * 128 + lane * 4);
            uint2 vd = *(const uint2*)(feat + (size_t)s3 * 128 + lane * 4);
            hacc(va.x, acc[0], acc[1]); hacc(va.y, acc[2], acc[3]);
            hacc(vb.x, acc[0], acc[1]); hacc(vb.y, acc[2], acc[3]);
            hacc(vc.x, acc[0], acc[1]); hacc(vc.y, acc[2], acc[3]);
            hacc(vd.x, acc[0], acc[1]); hacc(vd.y, acc[2], acc[3]);
        }
        for (; j < end; j++) {
            int s0 = g_adj[j];
            uint2 va = *(const uint2*)(feat + (size_t)s0 * 128 + lane * 4);
            hacc(va.x, acc[0], acc[1]); hacc(va.y, acc[2], acc[3]);
        }
        float sc = g_invdeg[w];
        *(uint2*)(g_agg16 + (size_t)w * 128 + lane * 4) =
            make_uint2(packh2(acc[0] * sc, acc[1] * sc), packh2(acc[2] * sc, acc[3] * sc));
    }
}

// ---------------- final: out[w] += mean-gather of P (g_h116, D=128 fp16) ----------------
__global__ void __launch_bounds__(256) agg_add(float* __restrict__ out, int n) {
    int w = (blockIdx.x * blockDim.x + threadIdx.x) >> 5;
    int lane = threadIdx.x & 31;
    if (w >= n) return;
    int j = g_rowptr[w], end = g_rowptr[w + 1];
    float acc[4] = {0.f, 0.f, 0.f, 0.f};
    for (; j + 3 < end; j += 4) {
        int s0 = g_adj[j], s1 = g_adj[j + 1], s2 = g_adj[j + 2], s3 = g_adj[j + 3];
        uint2 va = *(const uint2*)(g_h116 + (size_t)s0 * 128 + lane * 4);
        uint2 vb = *(const uint2*)(g_h116 + (size_t)s1 * 128 + lane * 4);
        uint2 vc = *(const uint2*)(g_h116 + (size_t)s2 * 128 + lane * 4);
        uint2 vd = *(const uint2*)(g_h116 + (size_t)s3 * 128 + lane * 4);
        hacc(va.x, acc[0], acc[1]); hacc(va.y, acc[2], acc[3]);
        hacc(vb.x, acc[0], acc[1]); hacc(vb.y, acc[2], acc[3]);
        hacc(vc.x, acc[0], acc[1]); hacc(vc.y, acc[2], acc[3]);
        hacc(vd.x, acc[0], acc[1]); hacc(vd.y, acc[2], acc[3]);
    }
    for (; j < end; j++) {
        int s0 = g_adj[j];
        uint2 va = *(const uint2*)(g_h116 + (size_t)s0 * 128 + lane * 4);
        hacc(va.x, acc[0], acc[1]); hacc(va.y, acc[2], acc[3]);
    }
    float sc = g_invdeg[w];
    float4* op = (float4*)(out + (size_t)w * 128 + lane * 4);
    float4 cur = *op;
    cur.x += acc[0] * sc; cur.y += acc[1] * sc;
    cur.z += acc[2] * sc; cur.w += acc[3] * sc;
    *op = cur;
}

// ---------------- tensor-core GEMM (fp16, 3-stage cp.async ring, 1 sync/chunk) ----------------
// DUAL:  out = act([agg16 | Ax] @ W + b), A halves stride KA/2.
// !DUAL: out = Ax @ W (+b per OUTMODE), A stride KA.
// OUTMODE: 0 = fp32 out_ext (+bias), 1 = fp16 plane out_sel (+bias),
//          2 = split: blockIdx.y==0 -> P fp16 to g_h116 (no bias), ==1 -> fp32 out_ext (+bias)
template <int KA, int N, bool DUAL, bool RELU, int OUTMODE>
__global__ void __launch_bounds__(256) gemm_mma(
    int x_sel, const float* __restrict__ bias,
    float* __restrict__ out_ext, int out_sel, int wboff, int M) {
    extern __shared__ __align__(16) __half smp[];
    // layout: sA stage s @ s*5120, sB stage s @ 15360 + s*5120 (in halves)
    const uint32_t smb = smem_u32(smp);

    const __half* Ax = sel_h(x_sel);
    constexpr int ASTRIDE = DUAL ? KA / 2 : KA;
    constexpr int CHUNKS = KA / 32;

    int tid = threadIdx.x;
    int wid = tid >> 5, lane = tid & 31;
    int bm = blockIdx.x * 128, bn = blockIdx.y * 128;
    int wm = (wid & 3) * 32;
    int wn = (wid >> 2) * 64;

    float acc[2][8][4];
    #pragma unroll
    for (int i = 0; i < 2; i++)
        #pragma unroll
        for (int j = 0; j < 8; j++)
            #pragma unroll
            for (int q = 0; q < 4; q++) acc[i][j][q] = 0.f;

    int lr = tid >> 1, lc = (tid & 1) * 16;
    int arow = bm + lr; if (arow >= M) arow = M - 1;
    const __half* wb = g_wf + wboff;

    auto issue = [&](int c, int st) {
        int kk = c * 32;
        const __half* ap;
        if (DUAL) {
            constexpr int K = KA / 2;
            const __half* Asrc = (kk < K) ? g_agg16 : Ax;
            int col0 = (kk < K) ? kk : (kk - K);
            ap = Asrc + (size_t)arow * ASTRIDE + col0 + lc;
        } else {
            ap = Ax + (size_t)arow * ASTRIDE + kk + lc;
        }
        uint32_t abase = smb + (uint32_t)(st * 5120 + lr * 40 + lc) * 2;
        cp16(abase, ap);
        cp16(abase + 16, ap + 8);
        const __half* bp = wb + (size_t)(bn + lr) * KA + kk + lc;
        uint32_t bbase = smb + (uint32_t)(15360 + st * 5120 + lr * 40 + lc) * 2;
        cp16(bbase, bp);
        cp16(bbase + 16, bp + 8);
        CP_COMMIT();
    };

    issue(0, 0);
    issue(1, 1);

    #pragma unroll 1
    for (int c = 0; c < CHUNKS; c++) {
        int st = c % 3;
        cp_wait<1>();        // group c done; group c+1 may remain in flight
        __syncthreads();     // all threads' group-c data visible; stage (c+2)%3 free of readers
        if (c + 2 < CHUNKS) issue(c + 2, (c + 2) % 3);
        else CP_COMMIT();    // empty group keeps the wait<1> accounting exact

        uint32_t sa = smb + (uint32_t)(st * 5120) * 2;
        uint32_t sb = smb + (uint32_t)(15360 + st * 5120) * 2;
        #pragma unroll
        for (int ks = 0; ks < 2; ks++) {
            int lrow = lane & 15, lcolsel = (lane >> 4) * 8 + ks * 16;
            uint32_t a[2][4];
            #pragma unroll
            for (int mi = 0; mi < 2; mi++)
                ldmx4(a[mi], sa + (uint32_t)((wm + mi * 16 + lrow) * 40 + lcolsel) * 2);
            #pragma unroll
            for (int nj = 0; nj < 4; nj++) {
                uint32_t bf[4];
                ldmx4(bf, sb + (uint32_t)((wn + nj * 16 + lrow) * 40 + lcolsel) * 2);
                #pragma unroll
                for (int mi = 0; mi < 2; mi++) {
                    mma16816(acc[mi][nj * 2],     a[mi], bf[0], bf[2]);
                    mma16816(acc[mi][nj * 2 + 1], a[mi], bf[1], bf[3]);
                }
            }
        }
    }

    // ---- epilogue ----
    int tg = lane & 3, g = lane >> 2;
    __half* out16 = (out_sel == 1) ? g_h116 : g_h216;
    bool isP = (OUTMODE == 2) && (blockIdx.y == 0);
    #pragma unroll
    for (int mi = 0; mi < 2; mi++) {
        int r0 = bm + wm + mi * 16 + g;
        int r1 = r0 + 8;
        #pragma unroll
        for (int ni = 0; ni < 8; ni++) {
            int col = bn + wn + ni * 8 + tg * 2;
            int colb = (OUTMODE == 2) ? (col & 127) : col;
            float b0 = isP ? 0.f : __ldg(&bias[colb]);
            float b1 = isP ? 0.f : __ldg(&bias[colb + 1]);
            float v0 = acc[mi][ni][0] + b0, v1 = acc[mi][ni][1] + b1;
            float v2 = acc[mi][ni][2] + b0, v3 = acc[mi][ni][3] + b1;
            if (RELU) {
                v0 = fmaxf(v0, 0.f); v1 = fmaxf(v1, 0.f);
                v2 = fmaxf(v2, 0.f); v3 = fmaxf(v3, 0.f);
            }
            if (OUTMODE == 0) {
                if (r0 < M) *(float2*)(out_ext + (size_t)r0 * N + col) = make_float2(v0, v1);
                if (r1 < M) *(float2*)(out_ext + (size_t)r1 * N + col) = make_float2(v2, v3);
            } else if (OUTMODE == 1) {
                if (r0 < M) *(uint32_t*)(out16 + (size_t)r0 * N + col) = packh2(v0, v1);
                if (r1 < M) *(uint32_t*)(out16 + (size_t)r1 * N + col) = packh2(v2, v3);
            } else {
                if (isP) {  // P -> g_h116, stride 128, fp16, no bias
                    if (r0 < M) *(uint32_t*)(g_h116 + (size_t)r0 * 128 + colb) = packh2(v0, v1);
                    if (r1 < M) *(uint32_t*)(g_h116 + (size_t)r1 * 128 + colb) = packh2(v2, v3);
                } else {    // Q + b2 -> fp32 out, stride 128
                    if (r0 < M) *(float2*)(out_ext + (size_t)r0 * 128 + colb) = make_float2(v0, v1);
                    if (r1 < M) *(float2*)(out_ext + (size_t)r1 * 128 + colb) = make_float2(v2, v3);
                }
            }
        }
    }
}

// ---------------- launch ----------------
extern "C" void kernel_launch(void* const* d_in, const int* in_sizes, int n_in,
                              void* d_out, int out_size) {
    const float* x   = (const float*)d_in[0];
    const int*   ei  = (const int*)d_in[1];     // int32 edge_index [2, E]
    const float* Wl0 = (const float*)d_in[2];
    const float* b0  = (const float*)d_in[3];
    const float* Wr0 = (const float*)d_in[4];
    const float* Wl1 = (const float*)d_in[5];
    const float* b1  = (const float*)d_in[6];
    const float* Wr1 = (const float*)d_in[7];
    const float* Wl2 = (const float*)d_in[8];
    const float* b2  = (const float*)d_in[9];
    const float* Wr2 = (const float*)d_in[10];
    float* out = (float*)d_out;

    const int E = in_sizes[1] / 2;
    const int M = in_sizes[0] / 128;
    const int* src = ei;
    const int* dst = ei + E;
    const int nb = (M + 1023) / 1024;
    const int SMEM = 3 * 5120 * 2 * 2;   // 61440 bytes (3 stages x (A+B) x 5120 halves)

    cudaFuncSetAttribute(gemm_mma<256, 256, true, true, 1>,
                         cudaFuncAttributeMaxDynamicSharedMemorySize, SMEM);
    cudaFuncSetAttribute(gemm_mma<512, 256, true, true, 1>,
                         cudaFuncAttributeMaxDynamicSharedMemorySize, SMEM);
    cudaFuncSetAttribute(gemm_mma<256, 256, false, false, 2>,
                         cudaFuncAttributeMaxDynamicSharedMemorySize, SMEM);

    // --- CSR build (merged init kernels; hierarchical scan; invdeg fused into scan3) ---
    init_zero_prep<<<1024, 256>>>(Wl0, Wr0, Wl1, Wr1, Wl2, Wr2, M);
    hist_conv<<<2048, 256>>>(dst, x, E, M, M * 32);
    scan1<<<nb, 1024>>>(M);
    scan2<<<1, 128>>>(nb);
    scan3<<<(M + 255) / 256, 256>>>(M);
    fill_kernel<<<2048, 256>>>(src, dst, E, M);

    const int agg_blocks = (M * 32 + 255) / 256;
    dim3 g2((M + 127) / 128, 2);

    // --- layer 0: 128 -> 256, relu ---
    aggregate_kernel<128><<<agg_blocks, 256>>>(0, M);
    gemm_mma<256, 256, true, true, 1><<<g2, 256, SMEM>>>(0, b0, nullptr, 1, 0, M);

    // --- layer 1: 256 -> 256, relu ---
    aggregate_kernel<256><<<agg_blocks, 256>>>(1, M);
    gemm_mma<512, 256, true, true, 1><<<g2, 256, SMEM>>>(1, b1, nullptr, 2, 65536, M);

    // --- layer 2 (commuted): [P|Q] = h2 @ [Wl2|Wr2]; out = Q + b2; out += mean-gather(P) ---
    gemm_mma<256, 256, false, false, 2><<<g2, 256, SMEM>>>(2, b2, out, 0, 196608, M);
    agg_add<<<agg_blocks, 256>>>(out, M);
}

// round 17
// speedup vs baseline: 1.5215x; 1.0171x over previous
#include <cuda_runtime.h>
#include <cuda_fp16.h>
#include <cstdint>

#define NN 100000
#define NE 1600000

// ---------------- device scratch (allocation-free; ONLY touched from device code) ----------------
__device__ int   g_degi[NN];
__device__ int   g_rowptr[NN + 1];
__device__ int   g_cursor[NN];
__device__ int   g_adj[NE];
__device__ int   g_rtmp[NN];
__device__ int   g_bsum[128];
__device__ __align__(16) float  g_invdeg[NN];
// fp16 activations
__device__ __align__(16) __half g_x16[(size_t)NN * 128];
__device__ __align__(16) __half g_h116[(size_t)NN * 256];   // h1; reused as P in layer 2
__device__ __align__(16) __half g_h216[(size_t)NN * 256];
__device__ __align__(16) __half g_agg16[(size_t)NN * 256];
// fp16 weights: L0 [256][256]@0, L1 [256][512]@65536, L2 packed [256][256]@196608
__device__ __align__(16) __half g_wf[262144];

// fp16 plane selectors: 0 = g_x16, 1 = g_h116, 2 = g_h216
__device__ __forceinline__ const __half* sel_h(int sel) {
    if (sel == 1) return g_h116;
    if (sel == 2) return g_h216;
    return g_x16;
}

// ---------------- helpers ----------------
__device__ __forceinline__ void hacc(uint32_t u, float& a, float& b) {
    __half2 t = *reinterpret_cast<__half2*>(&u);
    float2 f = __half22float2(t);
    a += f.x; b += f.y;
}
__device__ __forceinline__ uint32_t packh2(float a, float b) {
    __half2 t = __floats2half2_rn(a, b);
    return *reinterpret_cast<uint32_t*>(&t);
}
__device__ __forceinline__ uint32_t smem_u32(const void* p) {
    uint32_t r;
    asm("{ .reg .u64 t; cvta.to.shared.u64 t, %1; cvt.u32.u64 %0, t; }" : "=r"(r) : "l"(p));
    return r;
}
__device__ __forceinline__ void cp16(uint32_t smem, const void* g) {
    asm volatile("cp.async.cg.shared.global [%0], [%1], 16;"
                 :: "r"(smem), "l"(g) : "memory");
}
#define CP_COMMIT() asm volatile("cp.async.commit_group;" ::: "memory")
template <int Nw>
__device__ __forceinline__ void cp_wait() {
    asm volatile("cp.async.wait_group %0;" :: "n"(Nw) : "memory");
}
__device__ __forceinline__ void ldmx4(uint32_t* r, uint32_t addr) {
    asm volatile("ldmatrix.sync.aligned.m8n8.x4.shared.b16 {%0,%1,%2,%3}, [%4];"
                 : "=r"(r[0]), "=r"(r[1]), "=r"(r[2]), "=r"(r[3]) : "r"(addr));
}
__device__ __forceinline__ void mma16816(float* c, const uint32_t* a, uint32_t b0, uint32_t b1) {
    asm volatile("mma.sync.aligned.m16n8k16.row.col.f32.f16.f16.f32 "
                 "{%0,%1,%2,%3}, {%4,%5,%6,%7}, {%8,%9}, {%0,%1,%2,%3};"
                 : "+f"(c[0]), "+f"(c[1]), "+f"(c[2]), "+f"(c[3])
                 : "r"(a[0]), "r"(a[1]), "r"(a[2]), "r"(a[3]), "r"(b0), "r"(b1));
}

// ---------------- CSR build ----------------
__global__ void scan1(int n) {
    __shared__ int ws[32];
    int b = blockIdx.x, tid = threadIdx.x;
    int lane = tid & 31, wid = tid >> 5;
    int i = b * 1024 + tid;
    int v = (i < n) ? g_degi[i] : 0;
    int s = v;
    #pragma unroll
    for (int off = 1; off < 32; off <<= 1) {
        int t = __shfl_up_sync(0xffffffffu, s, off);
        if (lane >= off) s += t;
    }
    if (lane == 31) ws[wid] = s;
    __syncthreads();
    if (wid == 0) {
        int t2 = (lane < 32) ? ws[lane] : 0;
        #pragma unroll
        for (int off = 1; off < 32; off <<= 1) {
            int t = __shfl_up_sync(0xffffffffu, t2, off);
            if (lane >= off) t2 += t;
        }
        ws[lane] = t2;
    }
    __syncthreads();
    int excl = s - v + (wid ? ws[wid - 1] : 0);
    if (i < n) g_rtmp[i] = excl;
    if (tid == 1023) g_bsum[b] = excl + v;
}
__global__ void scan2(int nb) {
    __shared__ int ws[4];
    int tid = threadIdx.x, lane = tid & 31, wid = tid >> 5;
    int v = (tid < nb) ? g_bsum[tid] : 0;
    int s = v;
    #pragma unroll
    for (int off = 1; off < 32; off <<= 1) {
        int t = __shfl_up_sync(0xffffffffu, s, off);
        if (lane >= off) s += t;
    }
    if (lane == 31) ws[wid] = s;
    __syncthreads();
    if (tid == 0) {
        int a = 0;
        #pragma unroll
        for (int q = 0; q < 4; q++) { int t = ws[q]; ws[q] = a; a += t; }
    }
    __syncthreads();
    int excl = s - v + ws[wid];
    if (tid < nb) g_bsum[tid] = excl;
}
// scan3 + invdeg fused
__global__ void scan3(int n) {
    int i = blockIdx.x * blockDim.x + threadIdx.x;
    if (i < n) {
        int deg = g_degi[i];
        int r = g_rtmp[i] + g_bsum[i >> 10];
        g_rowptr[i] = r;
        g_cursor[i] = r;
        g_invdeg[i] = 1.0f / fmaxf((float)deg, 1.0f);
        if (i == n - 1) g_rowptr[n] = r + deg;
    }
}
__global__ void fill_kernel(const int* __restrict__ src, const int* __restrict__ dst, int E, int n) {
    int i = blockIdx.x * blockDim.x + threadIdx.x;
    int stride = gridDim.x * blockDim.x;
    for (; i < E; i += stride) {
        int d = dst[i], s = src[i];
        if ((unsigned)d < (unsigned)n && (unsigned)s < (unsigned)n) {
            int slot = atomicAdd(&g_cursor[d], 1);
            if ((unsigned)slot < (unsigned)NE) g_adj[slot] = s;
        }
    }
}

// ---------------- merged init: zero degi + split all weights ----------------
__global__ void init_zero_prep(const float* __restrict__ Wl0, const float* __restrict__ Wr0,
                               const float* __restrict__ Wl1, const float* __restrict__ Wr1,
                               const float* __restrict__ Wl2, const float* __restrict__ Wr2,
                               int M) {
    int total = M + 262144;
    for (int i = blockIdx.x * blockDim.x + threadIdx.x; i < total; i += gridDim.x * blockDim.x) {
        if (i < M) { g_degi[i] = 0; continue; }
        int j = i - M;
        float w;
        if (j < 65536) {            // L0: K2=256
            int n = j >> 8, k = j & 255;
            w = (k < 128) ? Wl0[(size_t)k * 256 + n] : Wr0[(size_t)(k - 128) * 256 + n];
        } else if (j < 196608) {    // L1: K2=512
            int q = j - 65536;
            int n = q >> 9, k = q & 511;
            w = (k < 256) ? Wl1[(size_t)k * 256 + n] : Wr1[(size_t)(k - 256) * 256 + n];
        } else {                    // L2 packed: rows 0-127 Wl2 cols, 128-255 Wr2 cols; K=256
            int q = j - 196608;
            int n = q >> 8, k = q & 255;
            w = (n < 128) ? Wl2[(size_t)k * 128 + n] : Wr2[(size_t)k * 128 + (n - 128)];
        }
        g_wf[j] = __float2half(w);
    }
}
// ---------------- merged: histogram + x->fp16 convert ----------------
__global__ void hist_conv(const int* __restrict__ dst, const float* __restrict__ x,
                          int E, int n, int total4) {
    int total = E + total4;
    for (int i = blockIdx.x * blockDim.x + threadIdx.x; i < total; i += gridDim.x * blockDim.x) {
        if (i < E) {
            int d = dst[i];
            if ((unsigned)d < (unsigned)n) atomicAdd(&g_degi[d], 1);
        } else {
            int j = i - E;
            float4 v = *(const float4*)(x + (size_t)j * 4);
            *(uint2*)(g_x16 + (size_t)j * 4) = make_uint2(packh2(v.x, v.y), packh2(v.z, v.w));
        }
    }
}

// ---------------- mean aggregation: fp16 gather (8-deep MLP), fp32 acc, fp16 write ----------------
template <int D>
__global__ void __launch_bounds__(256) aggregate_kernel(int src_sel, int n) {
    const __half* feat = sel_h(src_sel);
    int w = (blockIdx.x * blockDim.x + threadIdx.x) >> 5;
    int lane = threadIdx.x & 31;
    if (w >= n) return;
    int j = g_rowptr[w], end = g_rowptr[w + 1];

    if (D == 256) {
        float acc[8] = {0.f, 0.f, 0.f, 0.f, 0.f, 0.f, 0.f, 0.f};
        for (; j + 7 < end; j += 8) {
            int sv[8];
            #pragma unroll
            for (int q = 0; q < 8; q++) sv[q] = g_adj[j + q];
            uint4 v[8];
            #pragma unroll
            for (int q = 0; q < 8; q++)
                v[q] = *(const uint4*)(feat + (size_t)sv[q] * 256 + lane * 8);
            #pragma unroll
            for (int q = 0; q < 8; q++) {
                hacc(v[q].x, acc[0], acc[1]); hacc(v[q].y, acc[2], acc[3]);
                hacc(v[q].z, acc[4], acc[5]); hacc(v[q].w, acc[6], acc[7]);
            }
        }
        for (; j + 1 < end; j += 2) {
            int s0 = g_adj[j], s1 = g_adj[j + 1];
            uint4 va = *(const uint4*)(feat + (size_t)s0 * 256 + lane * 8);
            uint4 vb = *(const uint4*)(feat + (size_t)s1 * 256 + lane * 8);
            hacc(va.x, acc[0], acc[1]); hacc(va.y, acc[2], acc[3]);
            hacc(va.z, acc[4], acc[5]); hacc(va.w, acc[6], acc[7]);
            hacc(vb.x, acc[0], acc[1]); hacc(vb.y, acc[2], acc[3]);
            hacc(vb.z, acc[4], acc[5]); hacc(vb.w, acc[6], acc[7]);
        }
        if (j < end) {
            int s0 = g_adj[j];
            uint4 va = *(const uint4*)(feat + (size_t)s0 * 256 + lane * 8);
            hacc(va.x, acc[0], acc[1]); hacc(va.y, acc[2], acc[3]);
            hacc(va.z, acc[4], acc[5]); hacc(va.w, acc[6], acc[7]);
        }
        float sc = g_invdeg[w];
        uint4 o;
        o.x = packh2(acc[0] * sc, acc[1] * sc);
        o.y = packh2(acc[2] * sc, acc[3] * sc);
        o.z = packh2(acc[4] * sc, acc[5] * sc);
        o.w = packh2(acc[6] * sc, acc[7] * sc);
        *(uint4*)(g_agg16 + (size_t)w * 256 + lane * 8) = o;
    } else {
        float acc[4] = {0.f, 0.f, 0.f, 0.f};
        for (; j + 7 < end; j += 8) {
            int sv[8];
            #pragma unroll
            for (int q = 0; q < 8; q++) sv[q] = g_adj[j + q];
            uint2 v[8];
            #pragma unroll
            for (int q = 0; q < 8; q++)
                v[q] = *(const uint2*)(feat + (size_t)sv[q] * 128 + lane * 4);
            #pragma unroll
            for (int q = 0; q < 8; q++) {
                hacc(v[q].x, acc[0], acc[1]); hacc(v[q].y, acc[2], acc[3]);
            }
        }
        for (; j + 1 < end; j += 2) {
            int s0 = g_adj[j], s1 = g_adj[j + 1];
            uint2 va = *(const uint2*)(feat + (size_t)s0 * 128 + lane * 4);
            uint2 vb = *(const uint2*)(feat + (size_t)s1 * 128 + lane * 4);
            hacc(va.x, acc[0], acc[1]); hacc(va.y, acc[2], acc[3]);
            hacc(vb.x, acc[0], acc[1]); hacc(vb.y, acc[2], acc[3]);
        }
        if (j < end) {
            int s0 = g_adj[j];
            uint2 va = *(const uint2*)(feat + (size_t)s0 * 128 + lane * 4);
            hacc(va.x, acc[0], acc[1]); hacc(va.y, acc[2], acc[3]);
        }
        float sc = g_invdeg[w];
        *(uint2*)(g_agg16 + (size_t)w * 128 + lane * 4) =
            make_uint2(packh2(acc[0] * sc, acc[1] * sc), packh2(acc[2] * sc, acc[3] * sc));
    }
}

// ---------------- final: out[w] += mean-gather of P (g_h116, D=128 fp16, 8-deep MLP) ----------------
__global__ void __launch_bounds__(256) agg_add(float* __restrict__ out, int n) {
    int w = (blockIdx.x * blockDim.x + threadIdx.x) >> 5;
    int lane = threadIdx.x & 31;
    if (w >= n) return;
    int j = g_rowptr[w], end = g_rowptr[w + 1];
    float acc[4] = {0.f, 0.f, 0.f, 0.f};
    for (; j + 7 < end; j += 8) {
        int sv[8];
        #pragma unroll
        for (int q = 0; q < 8; q++) sv[q] = g_adj[j + q];
        uint2 v[8];
        #pragma unroll
        for (int q = 0; q < 8; q++)
            v[q] = *(const uint2*)(g_h116 + (size_t)sv[q] * 128 + lane * 4);
        #pragma unroll
        for (int q = 0; q < 8; q++) {
            hacc(v[q].x, acc[0], acc[1]); hacc(v[q].y, acc[2], acc[3]);
        }
    }
    for (; j + 1 < end; j += 2) {
        int s0 = g_adj[j], s1 = g_adj[j + 1];
        uint2 va = *(const uint2*)(g_h116 + (size_t)s0 * 128 + lane * 4);
        uint2 vb = *(const uint2*)(g_h116 + (size_t)s1 * 128 + lane * 4);
        hacc(va.x, acc[0], acc[1]); hacc(va.y, acc[2], acc[3]);
        hacc(vb.x, acc[0], acc[1]); hacc(vb.y, acc[2], acc[3]);
    }
    if (j < end) {
        int s0 = g_adj[j];
        uint2 va = *(const uint2*)(g_h116 + (size_t)s0 * 128 + lane * 4);
        hacc(va.x, acc[0], acc[1]); hacc(va.y, acc[2], acc[3]);
    }
    float sc = g_invdeg[w];
    float4* op = (float4*)(out + (size_t)w * 128 + lane * 4);
    float4 cur = *op;
    cur.x += acc[0] * sc; cur.y += acc[1] * sc;
    cur.z += acc[2] * sc; cur.w += acc[3] * sc;
    *op = cur;
}

// ---------------- tensor-core GEMM (fp16, 3-stage cp.async ring, 1 sync/chunk) ----------------
// DUAL:  out = act([agg16 | Ax] @ W + b), A halves stride KA/2.
// !DUAL: out = Ax @ W (+b per OUTMODE), A stride KA.
// OUTMODE: 0 = fp32 out_ext (+bias), 1 = fp16 plane out_sel (+bias),
//          2 = split: blockIdx.y==0 -> P fp16 to g_h116 (no bias), ==1 -> fp32 out_ext (+bias)
template <int KA, int N, bool DUAL, bool RELU, int OUTMODE>
__global__ void __launch_bounds__(256) gemm_mma(
    int x_sel, const float* __restrict__ bias,
    float* __restrict__ out_ext, int out_sel, int wboff, int M) {
    extern __shared__ __align__(16) __half smp[];
    // layout: sA stage s @ s*5120, sB stage s @ 15360 + s*5120 (in halves)
    const uint32_t smb = smem_u32(smp);

    const __half* Ax = sel_h(x_sel);
    constexpr int ASTRIDE = DUAL ? KA / 2 : KA;
    constexpr int CHUNKS = KA / 32;

    int tid = threadIdx.x;
    int wid = tid >> 5, lane = tid & 31;
    int bm = blockIdx.x * 128, bn = blockIdx.y * 128;
    int wm = (wid & 3) * 32;
    int wn = (wid >> 2) * 64;

    float acc[2][8][4];
    #pragma unroll
    for (int i = 0; i < 2; i++)
        #pragma unroll
        for (int j = 0; j < 8; j++)
            #pragma unroll
            for (int q = 0; q < 4; q++) acc[i][j][q] = 0.f;

    int lr = tid >> 1, lc = (tid & 1) * 16;
    int arow = bm + lr; if (arow >= M) arow = M - 1;
    const __half* wb = g_wf + wboff;

    auto issue = [&](int c, int st) {
        int kk = c * 32;
        const __half* ap;
        if (DUAL) {
            constexpr int K = KA / 2;
            const __half* Asrc = (kk < K) ? g_agg16 : Ax;
            int col0 = (kk < K) ? kk : (kk - K);
            ap = Asrc + (size_t)arow * ASTRIDE + col0 + lc;
        } else {
            ap = Ax + (size_t)arow * ASTRIDE + kk + lc;
        }
        uint32_t abase = smb + (uint32_t)(st * 5120 + lr * 40 + lc) * 2;
        cp16(abase, ap);
        cp16(abase + 16, ap + 8);
        const __half* bp = wb + (size_t)(bn + lr) * KA + kk + lc;
        uint32_t bbase = smb + (uint32_t)(15360 + st * 5120 + lr * 40 + lc) * 2;
        cp16(bbase, bp);
        cp16(bbase + 16, bp + 8);
        CP_COMMIT();
    };

    issue(0, 0);
    issue(1, 1);

    #pragma unroll 1
    for (int c = 0; c < CHUNKS; c++) {
        int st = c % 3;
        cp_wait<1>();        // group c done; group c+1 may remain in flight
        __syncthreads();     // all threads' group-c data visible; stage (c+2)%3 free of readers
        if (c + 2 < CHUNKS) issue(c + 2, (c + 2) % 3);
        else CP_COMMIT();    // empty group keeps the wait<1> accounting exact

        uint32_t sa = smb + (uint32_t)(st * 5120) * 2;
        uint32_t sb = smb + (uint32_t)(15360 + st * 5120) * 2;
        #pragma unroll
        for (int ks = 0; ks < 2; ks++) {
            int lrow = lane & 15, lcolsel = (lane >> 4) * 8 + ks * 16;
            uint32_t a[2][4];
            #pragma unroll
            for (int mi = 0; mi < 2; mi++)
                ldmx4(a[mi], sa + (uint32_t)((wm + mi * 16 + lrow) * 40 + lcolsel) * 2);
            #pragma unroll
            for (int nj = 0; nj < 4; nj++) {
                uint32_t bf[4];
                ldmx4(bf, sb + (uint32_t)((wn + nj * 16 + lrow) * 40 + lcolsel) * 2);
                #pragma unroll
                for (int mi = 0; mi < 2; mi++) {
                    mma16816(acc[mi][nj * 2],     a[mi], bf[0], bf[2]);
                    mma16816(acc[mi][nj * 2 + 1], a[mi], bf[1], bf[3]);
                }
            }
        }
    }

    // ---- epilogue ----
    int tg = lane & 3, g = lane >> 2;
    __half* out16 = (out_sel == 1) ? g_h116 : g_h216;
    bool isP = (OUTMODE == 2) && (blockIdx.y == 0);
    #pragma unroll
    for (int mi = 0; mi < 2; mi++) {
        int r0 = bm + wm + mi * 16 + g;
        int r1 = r0 + 8;
        #pragma unroll
        for (int ni = 0; ni < 8; ni++) {
            int col = bn + wn + ni * 8 + tg * 2;
            int colb = (OUTMODE == 2) ? (col & 127) : col;
            float b0 = isP ? 0.f : __ldg(&bias[colb]);
            float b1 = isP ? 0.f : __ldg(&bias[colb + 1]);
            float v0 = acc[mi][ni][0] + b0, v1 = acc[mi][ni][1] + b1;
            float v2 = acc[mi][ni][2] + b0, v3 = acc[mi][ni][3] + b1;
            if (RELU) {
                v0 = fmaxf(v0, 0.f); v1 = fmaxf(v1, 0.f);
                v2 = fmaxf(v2, 0.f); v3 = fmaxf(v3, 0.f);
            }
            if (OUTMODE == 0) {
                if (r0 < M) *(float2*)(out_ext + (size_t)r0 * N + col) = make_float2(v0, v1);
                if (r1 < M) *(float2*)(out_ext + (size_t)r1 * N + col) = make_float2(v2, v3);
            } else if (OUTMODE == 1) {
                if (r0 < M) *(uint32_t*)(out16 + (size_t)r0 * N + col) = packh2(v0, v1);
                if (r1 < M) *(uint32_t*)(out16 + (size_t)r1 * N + col) = packh2(v2, v3);
            } else {
                if (isP) {  // P -> g_h116, stride 128, fp16, no bias
                    if (r0 < M) *(uint32_t*)(g_h116 + (size_t)r0 * 128 + colb) = packh2(v0, v1);
                    if (r1 < M) *(uint32_t*)(g_h116 + (size_t)r1 * 128 + colb) = packh2(v2, v3);
                } else {    // Q + b2 -> fp32 out, stride 128
                    if (r0 < M) *(float2*)(out_ext + (size_t)r0 * 128 + colb) = make_float2(v0, v1);
                    if (r1 < M) *(float2*)(out_ext + (size_t)r1 * 128 + colb) = make_float2(v2, v3);
                }
            }
        }
    }
}

// ---------------- launch ----------------
extern "C" void kernel_launch(void* const* d_in, const int* in_sizes, int n_in,
                              void* d_out, int out_size) {
    const float* x   = (const float*)d_in[0];
    const int*   ei  = (const int*)d_in[1];     // int32 edge_index [2, E]
    const float* Wl0 = (const float*)d_in[2];
    const float* b0  = (const float*)d_in[3];
    const float* Wr0 = (const float*)d_in[4];
    const float* Wl1 = (const float*)d_in[5];
    const float* b1  = (const float*)d_in[6];
    const float* Wr1 = (const float*)d_in[7];
    const float* Wl2 = (const float*)d_in[8];
    const float* b2  = (const float*)d_in[9];
    const float* Wr2 = (const float*)d_in[10];
    float* out = (float*)d_out;

    const int E = in_sizes[1] / 2;
    const int M = in_sizes[0] / 128;
    const int* src = ei;
    const int* dst = ei + E;
    const int nb = (M + 1023) / 1024;
    const int SMEM = 3 * 5120 * 2 * 2;   // 61440 bytes (3 stages x (A+B) x 5120 halves)

    cudaFuncSetAttribute(gemm_mma<256, 256, true, true, 1>,
                         cudaFuncAttributeMaxDynamicSharedMemorySize, SMEM);
    cudaFuncSetAttribute(gemm_mma<512, 256, true, true, 1>,
                         cudaFuncAttributeMaxDynamicSharedMemorySize, SMEM);
    cudaFuncSetAttribute(gemm_mma<256, 256, false, false, 2>,
                         cudaFuncAttributeMaxDynamicSharedMemorySize, SMEM);

    // --- CSR build (merged init kernels; hierarchical scan; invdeg fused into scan3) ---
    init_zero_prep<<<1024, 256>>>(Wl0, Wr0, Wl1, Wr1, Wl2, Wr2, M);
    hist_conv<<<2048, 256>>>(dst, x, E, M, M * 32);
    scan1<<<nb, 1024>>>(M);
    scan2<<<1, 128>>>(nb);
    scan3<<<(M + 255) / 256, 256>>>(M);
    fill_kernel<<<2048, 256>>>(src, dst, E, M);

    const int agg_blocks = (M * 32 + 255) / 256;
    dim3 g2((M + 127) / 128, 2);

    // --- layer 0: 128 -> 256, relu ---
    aggregate_kernel<128><<<agg_blocks, 256>>>(0, M);
    gemm_mma<256, 256, true, true, 1><<<g2, 256, SMEM>>>(0, b0, nullptr, 1, 0, M);

    // --- layer 1: 256 -> 256, relu ---
    aggregate_kernel<256><<<agg_blocks, 256>>>(1, M);
    gemm_mma<512, 256, true, true, 1><<<g2, 256, SMEM>>>(1, b1, nullptr, 2, 65536, M);

    // --- layer 2 (commuted): [P|Q] = h2 @ [Wl2|Wr2]; out = Q + b2; out += mean-gather(P) ---
    gemm_mma<256, 256, false, false, 2><<<g2, 256, SMEM>>>(2, b2, out, 0, 196608, M);
    agg_add<<<agg_blocks, 256>>>(out, M);
}